// round 4
// baseline (speedup 1.0000x reference)
#include <cuda_runtime.h>
#include <math.h>

#define BSZ   2
#define SEQ   1024
#define DM    256
#define DI    512
#define DS    64
#define DTR   16
#define NTOK  (BSZ*SEQ)
#define XPN   (DTR + 2*DS)   // 144

// ---------------- scratch (static device memory; no allocations) -------------
__device__ float g_xn [NTOK*DM];
__device__ float g_xnr[NTOK*DM];
__device__ float g_xz [2][NTOK*2*DI];
__device__ float g_xc [2][NTOK*DI];
__device__ float g_dbl[2][NTOK*XPN];
__device__ float g_dt [2][NTOK*DI];
__device__ float g_y  [2][NTOK*DI];
__device__ float g_yp [2][NTOK*DM];
__device__ float g_x2 [NTOK*DM];

__device__ __forceinline__ float sigmoidf_(float x){ return 1.f/(1.f+__expf(-x)); }

// ---------------- LayerNorm #1 (writes normal + flipped order) ---------------
__global__ __launch_bounds__(256) void ln1_kernel(const float* __restrict__ x,
                                                  const float* __restrict__ g,
                                                  const float* __restrict__ bta){
  int m = blockIdx.x; int tid = threadIdx.x;
  int b = m / SEQ, s = m % SEQ;
  float v = x[m*DM + tid];
  __shared__ float s1[8], s2[8];
  float sum = v, sq = v*v;
  #pragma unroll
  for (int o=16;o;o>>=1){ sum += __shfl_xor_sync(~0u,sum,o); sq += __shfl_xor_sync(~0u,sq,o); }
  if ((tid&31)==0){ s1[tid>>5]=sum; s2[tid>>5]=sq; }
  __syncthreads();
  float tot=0.f, totq=0.f;
  #pragma unroll
  for(int i=0;i<8;i++){ tot+=s1[i]; totq+=s2[i]; }
  float mu  = tot*(1.f/DM);
  float var = totq*(1.f/DM) - mu*mu;
  float inv = rsqrtf(var + 1e-5f);
  float o = (v-mu)*inv*g[tid] + bta[tid];
  g_xn [m*DM + tid] = o;
  g_xnr[(b*SEQ + (SEQ-1-s))*DM + tid] = o;
}

// ---------------- combine fwd + flipped bwd, then LayerNorm #2 ---------------
__global__ __launch_bounds__(256) void combine_ln2_kernel(const float* __restrict__ g,
                                                          const float* __restrict__ bta){
  int m = blockIdx.x; int tid = threadIdx.x;
  int b = m / SEQ, s = m % SEQ;
  float v = g_yp[0][m*DM + tid] + g_yp[1][(b*SEQ + (SEQ-1-s))*DM + tid];
  __shared__ float s1[8], s2[8];
  float sum = v, sq = v*v;
  #pragma unroll
  for (int o=16;o;o>>=1){ sum += __shfl_xor_sync(~0u,sum,o); sq += __shfl_xor_sync(~0u,sq,o); }
  if ((tid&31)==0){ s1[tid>>5]=sum; s2[tid>>5]=sq; }
  __syncthreads();
  float tot=0.f, totq=0.f;
  #pragma unroll
  for(int i=0;i<8;i++){ tot+=s1[i]; totq+=s2[i]; }
  float mu  = tot*(1.f/DM);
  float var = totq*(1.f/DM) - mu*mu;
  float inv = rsqrtf(var + 1e-5f);
  g_x2[m*DM + tid] = (v-mu)*inv*g[tid] + bta[tid];
}

// ---------------- generic SGEMM: C = A(MxK,row) * B(NxK,row)^T ---------------
// mode 0: plain store; mode 1: gelu(C + bias)
#define BM 64
#define BN 64
#define BK 16
__global__ __launch_bounds__(256) void sgemm_nt(
    const float* __restrict__ A, const float* __restrict__ Bw, float* __restrict__ C,
    int M, int N, int K, int mode, const float* __restrict__ bias){
  __shared__ float As[BK][BM+4];
  __shared__ float Bs[BK][BN+4];
  int bm = blockIdx.y*BM, bn = blockIdx.x*BN;
  int tid = threadIdx.x;
  int lr = tid>>2;          // 0..63
  int lk = (tid&3)<<2;      // 0,4,8,12
  int ty = tid>>4, tx = tid&15;
  float acc[4][4];
  #pragma unroll
  for(int i=0;i<4;i++)
    #pragma unroll
    for(int j=0;j<4;j++) acc[i][j]=0.f;
  const float* Ap = A + (size_t)(bm+lr)*K + lk;
  bool bvalid = (bn+lr) < N;
  const float* Bp = Bw + (size_t)(bvalid ? (bn+lr) : 0)*K + lk;
  for (int k0=0; k0<K; k0+=BK){
    float4 a4 = *(const float4*)(Ap + k0);
    float4 b4 = make_float4(0.f,0.f,0.f,0.f);
    if (bvalid) b4 = *(const float4*)(Bp + k0);
    As[lk+0][lr]=a4.x; As[lk+1][lr]=a4.y; As[lk+2][lr]=a4.z; As[lk+3][lr]=a4.w;
    Bs[lk+0][lr]=b4.x; Bs[lk+1][lr]=b4.y; Bs[lk+2][lr]=b4.z; Bs[lk+3][lr]=b4.w;
    __syncthreads();
    #pragma unroll
    for(int k=0;k<BK;k++){
      float4 ar = *(const float4*)&As[k][ty<<2];
      float4 br = *(const float4*)&Bs[k][tx<<2];
      float a[4]={ar.x,ar.y,ar.z,ar.w}, bb[4]={br.x,br.y,br.z,br.w};
      #pragma unroll
      for(int i=0;i<4;i++)
        #pragma unroll
        for(int j=0;j<4;j++) acc[i][j] = fmaf(a[i],bb[j],acc[i][j]);
    }
    __syncthreads();
  }
  #pragma unroll
  for(int i=0;i<4;i++){
    int row = bm + (ty<<2) + i;
    #pragma unroll
    for(int j=0;j<4;j++){
      int col = bn + (tx<<2) + j;
      if (col < N){
        float v = acc[i][j];
        if (mode==1){
          v += bias[col];
          v = 0.5f*v*(1.f + erff(v*0.70710678118654752440f));
        }
        C[(size_t)row*N + col] = v;
      }
    }
  }
}

// ---------------- causal depthwise conv (D_CONV=4) + SiLU --------------------
__global__ __launch_bounds__(256) void conv_silu_kernel(
    const float* __restrict__ xz, const float* __restrict__ w,
    const float* __restrict__ cb, float* __restrict__ xc){
  int idx = blockIdx.x*blockDim.x + threadIdx.x;   // NTOK*DI
  int d = idx & (DI-1);
  int m = idx >> 9;
  int s = m & (SEQ-1);
  float acc = cb[d];
  float w0 = w[d*4+0], w1 = w[d*4+1], w2 = w[d*4+2], w3 = w[d*4+3];
  const float* xi = xz + (size_t)m*(2*DI) + d;     // token m, channel d
  if (s >= 3) acc = fmaf(w0, xi[-3*2*DI], acc);
  if (s >= 2) acc = fmaf(w1, xi[-2*2*DI], acc);
  if (s >= 1) acc = fmaf(w2, xi[-1*2*DI], acc);
  acc = fmaf(w3, xi[0], acc);
  xc[(size_t)m*DI + d] = acc * sigmoidf_(acc);
}

// ---------------- dt = softplus(dbl[:, :16] @ dt_w^T + dt_b) -----------------
__global__ __launch_bounds__(512) void dt_kernel(
    const float* __restrict__ dbl, const float* __restrict__ dtw,
    const float* __restrict__ dtb, float* __restrict__ dt){
  int m = blockIdx.x; int d = threadIdx.x;
  __shared__ float s16[DTR];
  if (d < DTR) s16[d] = dbl[(size_t)m*XPN + d];
  __syncthreads();
  float acc = dtb[d];
  #pragma unroll
  for(int r=0;r<DTR;r++) acc = fmaf(s16[r], dtw[d*DTR + r], acc);
  float sp = (acc > 20.f) ? acc : log1pf(__expf(acc));
  dt[(size_t)m*DI + d] = sp;
}

// ---------------- selective scan: warp per (dir,b,d), lane holds 2 states ----
__global__ __launch_bounds__(256) void scan_kernel(
    const float* __restrict__ Af, const float* __restrict__ Ab,
    const float* __restrict__ Dpf, const float* __restrict__ Dpb){
  int gw   = (blockIdx.x*blockDim.x + threadIdx.x)>>5;   // 0..2047
  int lane = threadIdx.x & 31;
  int dir = gw >> 10;
  int rem = gw & 1023;
  int b = rem >> 9;
  int d = rem & 511;
  const float* Alog = dir ? Ab : Af;
  const float* Dp   = dir ? Dpb : Dpf;
  const float* dt  = g_dt[dir];
  const float* xc  = g_xc[dir];
  const float* dbl = g_dbl[dir];
  const float* xz  = g_xz[dir];
  float*       y   = g_y[dir];

  float a0 = -__expf(Alog[d*DS + 2*lane + 0]);
  float a1 = -__expf(Alog[d*DS + 2*lane + 1]);
  float Dpd = Dp[d];
  float h0 = 0.f, h1 = 0.f;
  size_t r = (size_t)b*SEQ;
  const float* dblp = dbl + r*XPN + 2*lane;
  const float* dtp  = dt  + r*DI + d;
  const float* xcp  = xc  + r*DI + d;
  const float* zp   = xz  + r*2*DI + DI + d;
  float*       ypp  = y   + r*DI + d;

  for (int t=0; t<SEQ; t++){
    float2 Bm = *(const float2*)(dblp + DTR);
    float2 Cm = *(const float2*)(dblp + DTR + DS);
    float dtv = *dtp;
    float xcv = *xcp;
    float dA0 = __expf(dtv*a0);
    float dA1 = __expf(dtv*a1);
    float dbx = dtv*xcv;
    h0 = fmaf(dA0, h0, dbx*Bm.x);
    h1 = fmaf(dA1, h1, dbx*Bm.y);
    float part = fmaf(h0, Cm.x, h1*Cm.y);
    part += __shfl_xor_sync(~0u, part, 16);
    part += __shfl_xor_sync(~0u, part, 8);
    part += __shfl_xor_sync(~0u, part, 4);
    part += __shfl_xor_sync(~0u, part, 2);
    part += __shfl_xor_sync(~0u, part, 1);
    if (lane == 0){
      float zv = *zp;
      *ypp = (part + xcv*Dpd) * (zv * sigmoidf_(zv));
    }
    dblp += XPN; dtp += DI; xcp += DI; zp += 2*DI; ypp += DI;
  }
}

// ---------------- host orchestration ----------------------------------------
extern "C" void kernel_launch(void* const* d_in, const int* in_sizes, int n_in,
                              void* d_out, int out_size){
  (void)in_sizes; (void)n_in; (void)out_size;
  const float* x        = (const float*)d_in[0];
  const float* f_in_w   = (const float*)d_in[1];
  const float* f_conv_w = (const float*)d_in[2];
  const float* f_conv_b = (const float*)d_in[3];
  const float* f_xproj  = (const float*)d_in[4];
  const float* f_dt_w   = (const float*)d_in[5];
  const float* f_dt_b   = (const float*)d_in[6];
  const float* f_A_log  = (const float*)d_in[7];
  const float* f_Dp     = (const float*)d_in[8];
  const float* f_out_w  = (const float*)d_in[9];
  const float* b_in_w   = (const float*)d_in[10];
  const float* b_conv_w = (const float*)d_in[11];
  const float* b_conv_b = (const float*)d_in[12];
  const float* b_xproj  = (const float*)d_in[13];
  const float* b_dt_w   = (const float*)d_in[14];
  const float* b_dt_b   = (const float*)d_in[15];
  const float* b_A_log  = (const float*)d_in[16];
  const float* b_Dp     = (const float*)d_in[17];
  const float* b_out_w  = (const float*)d_in[18];
  const float* ln1_g    = (const float*)d_in[19];
  const float* ln1_b    = (const float*)d_in[20];
  const float* ln2_g    = (const float*)d_in[21];
  const float* ln2_b    = (const float*)d_in[22];
  const float* w2       = (const float*)d_in[23];
  const float* b2       = (const float*)d_in[24];

  float *p_xn,*p_xnr,*p_xz,*p_xc,*p_dbl,*p_dt,*p_y,*p_yp,*p_x2;
  cudaGetSymbolAddress((void**)&p_xn,  g_xn);
  cudaGetSymbolAddress((void**)&p_xnr, g_xnr);
  cudaGetSymbolAddress((void**)&p_xz,  g_xz);
  cudaGetSymbolAddress((void**)&p_xc,  g_xc);
  cudaGetSymbolAddress((void**)&p_dbl, g_dbl);
  cudaGetSymbolAddress((void**)&p_dt,  g_dt);
  cudaGetSymbolAddress((void**)&p_y,   g_y);
  cudaGetSymbolAddress((void**)&p_yp,  g_yp);
  cudaGetSymbolAddress((void**)&p_x2,  g_x2);
  float* p_xz1  = p_xz  + (size_t)NTOK*2*DI;
  float* p_xc1  = p_xc  + (size_t)NTOK*DI;
  float* p_dbl1 = p_dbl + (size_t)NTOK*XPN;
  float* p_dt1  = p_dt  + (size_t)NTOK*DI;
  float* p_y1   = p_y   + (size_t)NTOK*DI;
  float* p_yp1  = p_yp  + (size_t)NTOK*DM;

  // 1) LN1 (writes xn and flipped xn)
  ln1_kernel<<<NTOK,256>>>(x, ln1_g, ln1_b);

  // 2) in_proj both directions: (2048 x 1024) = xn @ in_w^T
  {
    dim3 grid(2*DI/BN, NTOK/BM);
    sgemm_nt<<<grid,256>>>(p_xn,  f_in_w, p_xz,  NTOK, 2*DI, DM, 0, nullptr);
    sgemm_nt<<<grid,256>>>(p_xnr, b_in_w, p_xz1, NTOK, 2*DI, DM, 0, nullptr);
  }

  // 3) depthwise causal conv + silu
  {
    int nthr = NTOK*DI;
    conv_silu_kernel<<<nthr/256,256>>>(p_xz,  f_conv_w, f_conv_b, p_xc);
    conv_silu_kernel<<<nthr/256,256>>>(p_xz1, b_conv_w, b_conv_b, p_xc1);
  }

  // 4) xproj: (2048 x 144) = xc @ xproj_w^T
  {
    dim3 grid((XPN+BN-1)/BN, NTOK/BM);
    sgemm_nt<<<grid,256>>>(p_xc,  f_xproj, p_dbl,  NTOK, XPN, DI, 0, nullptr);
    sgemm_nt<<<grid,256>>>(p_xc1, b_xproj, p_dbl1, NTOK, XPN, DI, 0, nullptr);
  }

  // 5) dt = softplus(dbl16 @ dt_w^T + dt_b)
  dt_kernel<<<NTOK,512>>>(p_dbl,  f_dt_w, f_dt_b, p_dt);
  dt_kernel<<<NTOK,512>>>(p_dbl1, b_dt_w, b_dt_b, p_dt1);

  // 6) selective scan, both directions (2048 warps)
  scan_kernel<<<(2048*32)/256,256>>>(f_A_log, b_A_log, f_Dp, b_Dp);

  // 7) out_proj: (2048 x 256) = y @ out_w^T
  {
    dim3 grid(DM/BN, NTOK/BM);
    sgemm_nt<<<grid,256>>>(p_y,  f_out_w, p_yp,  NTOK, DM, DI, 0, nullptr);
    sgemm_nt<<<grid,256>>>(p_y1, b_out_w, p_yp1, NTOK, DM, DI, 0, nullptr);
  }

  // 8) x_ssm = yp_f + flip(yp_b); LN2
  combine_ln2_kernel<<<NTOK,256>>>(ln2_g, ln2_b);

  // 9) final: gelu(x2 @ w2^T + b2) -> d_out
  {
    dim3 grid(DM/BN, NTOK/BM);
    sgemm_nt<<<grid,256>>>(p_x2, w2, (float*)d_out, NTOK, DM, DM, 1, b2);
  }
}

// round 5
// speedup vs baseline: 1.9180x; 1.9180x over previous
#include <cuda_runtime.h>
#include <math.h>

#define BSZ   2
#define SEQ   1024
#define DM    256
#define DI    512
#define DS    64
#define DTR   16
#define NTOK  (BSZ*SEQ)
#define XPN   (DTR + 2*DS)   // 144

// ---------------- scratch (static device memory; no allocations) -------------
__device__ float g_xn [NTOK*DM];
__device__ float g_xnr[NTOK*DM];
__device__ float g_xz [2][NTOK*2*DI];
__device__ float g_xc [2][NTOK*DI];
__device__ float g_dbl[2][NTOK*XPN];
__device__ float g_dt [2][NTOK*DI];
__device__ float g_y  [2][NTOK*DI];
__device__ float g_yp [2][NTOK*DM];
__device__ float g_x2 [NTOK*DM];

__device__ __forceinline__ float sigmoidf_(float x){ return 1.f/(1.f+__expf(-x)); }

// ---------------- LayerNorm #1 (writes normal + flipped order) ---------------
__global__ __launch_bounds__(256) void ln1_kernel(const float* __restrict__ x,
                                                  const float* __restrict__ g,
                                                  const float* __restrict__ bta){
  int m = blockIdx.x; int tid = threadIdx.x;
  int b = m / SEQ, s = m % SEQ;
  float v = x[m*DM + tid];
  __shared__ float s1[8], s2[8];
  float sum = v, sq = v*v;
  #pragma unroll
  for (int o=16;o;o>>=1){ sum += __shfl_xor_sync(~0u,sum,o); sq += __shfl_xor_sync(~0u,sq,o); }
  if ((tid&31)==0){ s1[tid>>5]=sum; s2[tid>>5]=sq; }
  __syncthreads();
  float tot=0.f, totq=0.f;
  #pragma unroll
  for(int i=0;i<8;i++){ tot+=s1[i]; totq+=s2[i]; }
  float mu  = tot*(1.f/DM);
  float var = totq*(1.f/DM) - mu*mu;
  float inv = rsqrtf(var + 1e-5f);
  float o = (v-mu)*inv*g[tid] + bta[tid];
  g_xn [m*DM + tid] = o;
  g_xnr[(b*SEQ + (SEQ-1-s))*DM + tid] = o;
}

// ---------------- combine fwd + flipped bwd, then LayerNorm #2 ---------------
__global__ __launch_bounds__(256) void combine_ln2_kernel(const float* __restrict__ g,
                                                          const float* __restrict__ bta){
  int m = blockIdx.x; int tid = threadIdx.x;
  int b = m / SEQ, s = m % SEQ;
  float v = g_yp[0][m*DM + tid] + g_yp[1][(b*SEQ + (SEQ-1-s))*DM + tid];
  __shared__ float s1[8], s2[8];
  float sum = v, sq = v*v;
  #pragma unroll
  for (int o=16;o;o>>=1){ sum += __shfl_xor_sync(~0u,sum,o); sq += __shfl_xor_sync(~0u,sq,o); }
  if ((tid&31)==0){ s1[tid>>5]=sum; s2[tid>>5]=sq; }
  __syncthreads();
  float tot=0.f, totq=0.f;
  #pragma unroll
  for(int i=0;i<8;i++){ tot+=s1[i]; totq+=s2[i]; }
  float mu  = tot*(1.f/DM);
  float var = totq*(1.f/DM) - mu*mu;
  float inv = rsqrtf(var + 1e-5f);
  g_x2[m*DM + tid] = (v-mu)*inv*g[tid] + bta[tid];
}

// ---------------- generic SGEMM: C = A(MxK,row) * B(NxK,row)^T ---------------
#define BM 64
#define BN 64
#define BK 16
// Dual-direction GEMM: blockIdx.z selects (A,B,C) set. Plain stores only.
__global__ __launch_bounds__(256) void sgemm_nt_dual(
    const float* __restrict__ A0, const float* __restrict__ B0, float* __restrict__ C0,
    const float* __restrict__ A1, const float* __restrict__ B1, float* __restrict__ C1,
    int M, int N, int K){
  __shared__ float As[BK][BM+4];
  __shared__ float Bs[BK][BN+4];
  const float* A  = blockIdx.z ? A1 : A0;
  const float* Bw = blockIdx.z ? B1 : B0;
  float*       C  = blockIdx.z ? C1 : C0;
  int bm = blockIdx.y*BM, bn = blockIdx.x*BN;
  int tid = threadIdx.x;
  int lr = tid>>2;
  int lk = (tid&3)<<2;
  int ty = tid>>4, tx = tid&15;
  float acc[4][4];
  #pragma unroll
  for(int i=0;i<4;i++)
    #pragma unroll
    for(int j=0;j<4;j++) acc[i][j]=0.f;
  const float* Ap = A + (size_t)(bm+lr)*K + lk;
  bool bvalid = (bn+lr) < N;
  const float* Bp = Bw + (size_t)(bvalid ? (bn+lr) : 0)*K + lk;
  for (int k0=0; k0<K; k0+=BK){
    float4 a4 = *(const float4*)(Ap + k0);
    float4 b4 = make_float4(0.f,0.f,0.f,0.f);
    if (bvalid) b4 = *(const float4*)(Bp + k0);
    As[lk+0][lr]=a4.x; As[lk+1][lr]=a4.y; As[lk+2][lr]=a4.z; As[lk+3][lr]=a4.w;
    Bs[lk+0][lr]=b4.x; Bs[lk+1][lr]=b4.y; Bs[lk+2][lr]=b4.z; Bs[lk+3][lr]=b4.w;
    __syncthreads();
    #pragma unroll
    for(int k=0;k<BK;k++){
      float4 ar = *(const float4*)&As[k][ty<<2];
      float4 br = *(const float4*)&Bs[k][tx<<2];
      float a[4]={ar.x,ar.y,ar.z,ar.w}, bb[4]={br.x,br.y,br.z,br.w};
      #pragma unroll
      for(int i=0;i<4;i++)
        #pragma unroll
        for(int j=0;j<4;j++) acc[i][j] = fmaf(a[i],bb[j],acc[i][j]);
    }
    __syncthreads();
  }
  #pragma unroll
  for(int i=0;i<4;i++){
    int row = bm + (ty<<2) + i;
    #pragma unroll
    for(int j=0;j<4;j++){
      int col = bn + (tx<<2) + j;
      if (col < N) C[(size_t)row*N + col] = acc[i][j];
    }
  }
}

// Single GEMM with fused bias+gelu epilogue (final layer).
__global__ __launch_bounds__(256) void sgemm_nt_gelu(
    const float* __restrict__ A, const float* __restrict__ Bw, float* __restrict__ C,
    int M, int N, int K, const float* __restrict__ bias){
  __shared__ float As[BK][BM+4];
  __shared__ float Bs[BK][BN+4];
  int bm = blockIdx.y*BM, bn = blockIdx.x*BN;
  int tid = threadIdx.x;
  int lr = tid>>2;
  int lk = (tid&3)<<2;
  int ty = tid>>4, tx = tid&15;
  float acc[4][4];
  #pragma unroll
  for(int i=0;i<4;i++)
    #pragma unroll
    for(int j=0;j<4;j++) acc[i][j]=0.f;
  const float* Ap = A + (size_t)(bm+lr)*K + lk;
  const float* Bp = Bw + (size_t)(bn+lr)*K + lk;
  for (int k0=0; k0<K; k0+=BK){
    float4 a4 = *(const float4*)(Ap + k0);
    float4 b4 = *(const float4*)(Bp + k0);
    As[lk+0][lr]=a4.x; As[lk+1][lr]=a4.y; As[lk+2][lr]=a4.z; As[lk+3][lr]=a4.w;
    Bs[lk+0][lr]=b4.x; Bs[lk+1][lr]=b4.y; Bs[lk+2][lr]=b4.z; Bs[lk+3][lr]=b4.w;
    __syncthreads();
    #pragma unroll
    for(int k=0;k<BK;k++){
      float4 ar = *(const float4*)&As[k][ty<<2];
      float4 br = *(const float4*)&Bs[k][tx<<2];
      float a[4]={ar.x,ar.y,ar.z,ar.w}, bb[4]={br.x,br.y,br.z,br.w};
      #pragma unroll
      for(int i=0;i<4;i++)
        #pragma unroll
        for(int j=0;j<4;j++) acc[i][j] = fmaf(a[i],bb[j],acc[i][j]);
    }
    __syncthreads();
  }
  #pragma unroll
  for(int i=0;i<4;i++){
    int row = bm + (ty<<2) + i;
    #pragma unroll
    for(int j=0;j<4;j++){
      int col = bn + (tx<<2) + j;
      float v = acc[i][j] + bias[col];
      v = 0.5f*v*(1.f + erff(v*0.70710678118654752440f));
      C[(size_t)row*N + col] = v;
    }
  }
}

// ---------------- causal depthwise conv (D_CONV=4) + SiLU, both dirs ---------
__global__ __launch_bounds__(256) void conv_silu_kernel(
    const float* __restrict__ wf, const float* __restrict__ cbf,
    const float* __restrict__ wb, const float* __restrict__ cbb){
  int dir = blockIdx.y;
  const float* w  = dir ? wb  : wf;
  const float* cb = dir ? cbb : cbf;
  const float* xz = g_xz[dir];
  float*       xc = g_xc[dir];
  int idx = blockIdx.x*blockDim.x + threadIdx.x;   // NTOK*DI
  int d = idx & (DI-1);
  int m = idx >> 9;
  int s = m & (SEQ-1);
  float acc = cb[d];
  float w0 = w[d*4+0], w1 = w[d*4+1], w2 = w[d*4+2], w3 = w[d*4+3];
  const float* xi = xz + (size_t)m*(2*DI) + d;
  if (s >= 3) acc = fmaf(w0, xi[-3*2*DI], acc);
  if (s >= 2) acc = fmaf(w1, xi[-2*2*DI], acc);
  if (s >= 1) acc = fmaf(w2, xi[-1*2*DI], acc);
  acc = fmaf(w3, xi[0], acc);
  xc[(size_t)m*DI + d] = acc * sigmoidf_(acc);
}

// ---------------- dt = softplus(dbl[:, :16] @ dt_w^T + dt_b), both dirs ------
__global__ __launch_bounds__(512) void dt_kernel(
    const float* __restrict__ dtwf, const float* __restrict__ dtbf,
    const float* __restrict__ dtwb, const float* __restrict__ dtbb){
  int dir = blockIdx.x >> 11;            // 2048 blocks per dir
  int m   = blockIdx.x & (NTOK-1);
  const float* dtw = dir ? dtwb : dtwf;
  const float* dtb = dir ? dtbb : dtbf;
  const float* dbl = g_dbl[dir];
  float*       dt  = g_dt[dir];
  int d = threadIdx.x;
  __shared__ float s16[DTR];
  if (d < DTR) s16[d] = dbl[(size_t)m*XPN + d];
  __syncthreads();
  float acc = dtb[d];
  #pragma unroll
  for(int r=0;r<DTR;r++) acc = fmaf(s16[r], dtw[d*DTR + r], acc);
  float sp = (acc > 20.f) ? acc : log1pf(__expf(acc));
  dt[(size_t)m*DI + d] = sp;
}

// ---------------- selective scan, smem-tiled ---------------------------------
// Block = 64 threads handles (dir, b, 8 channels). Thread = 8 states of one
// channel. Per 32-timestep tile: cooperative coalesced staging of B/C/dt/xc/z
// into smem, then the serial recurrence runs from smem. Output gated+staged,
// written back per tile.
#define SCH 8        // channels per block
#define STG 8        // threads per channel
#define SNS 8        // states per thread
#define STT 32       // timesteps per tile
__global__ __launch_bounds__(64) void scan_kernel(
    const float* __restrict__ Af, const float* __restrict__ Ab,
    const float* __restrict__ Dpf, const float* __restrict__ Dpb){
  __shared__ float sB [STT][DS];
  __shared__ float sC [STT][DS];
  __shared__ float sdt[STT][SCH];
  __shared__ float sxc[STT][SCH];
  __shared__ float sz [STT][SCH];
  __shared__ float sy [STT][SCH];

  int blk = blockIdx.x;                 // 0..255
  int dir = blk >> 7;
  int b   = (blk >> 6) & 1;
  int cg  = blk & 63;                   // channel group
  int tid = threadIdx.x;
  int c   = tid >> 3;                   // local channel 0..7
  int g   = tid & 7;                    // state group 0..7
  int d   = cg*SCH + c;                 // global channel
  int n0  = g*SNS;

  const float* Alog = dir ? Ab : Af;
  const float* Dp   = dir ? Dpb : Dpf;
  const float* dt  = g_dt[dir];
  const float* xc  = g_xc[dir];
  const float* dbl = g_dbl[dir];
  const float* xz  = g_xz[dir];
  float*       y   = g_y[dir];
  size_t r = (size_t)b*SEQ;

  float a[SNS], h[SNS];
  #pragma unroll
  for(int j=0;j<SNS;j++){
    a[j] = -__expf(Alog[d*DS + n0 + j]);
    h[j] = 0.f;
  }
  float Dpd = Dp[d];

  for (int t0=0; t0<SEQ; t0+=STT){
    // ---- stage B/C: 32 t x 128 floats = 1024 float4, coalesced ----
    #pragma unroll
    for (int k=tid; k<STT*32; k+=64){
      int t  = k >> 5;
      int n4 = k & 31;
      float4 v = *(const float4*)(dbl + (r+t0+t)*XPN + DTR + n4*4);
      if (n4 < 16) *(float4*)&sB[t][n4*4]      = v;
      else         *(float4*)&sC[t][(n4-16)*4] = v;
    }
    // ---- stage dt/xc/z: 32 t x 8 ch each ----
    #pragma unroll
    for (int k=tid; k<STT*SCH; k+=64){
      int t = k >> 3;
      int cc = k & 7;
      int dd = cg*SCH + cc;
      sdt[t][cc] = dt[(r+t0+t)*DI + dd];
      sxc[t][cc] = xc[(r+t0+t)*DI + dd];
      sz [t][cc] = xz[(r+t0+t)*2*DI + DI + dd];
    }
    __syncthreads();

    #pragma unroll 4
    for (int t=0; t<STT; t++){
      float dtv = sdt[t][c];
      float xcv = sxc[t][c];
      float dbx = dtv * xcv;
      float4 b0 = *(const float4*)&sB[t][n0];
      float4 b1 = *(const float4*)&sB[t][n0+4];
      float4 c0 = *(const float4*)&sC[t][n0];
      float4 c1 = *(const float4*)&sC[t][n0+4];
      float Bv[8] = {b0.x,b0.y,b0.z,b0.w,b1.x,b1.y,b1.z,b1.w};
      float Cv[8] = {c0.x,c0.y,c0.z,c0.w,c1.x,c1.y,c1.z,c1.w};
      float part = 0.f;
      #pragma unroll
      for(int j=0;j<SNS;j++){
        float dA = __expf(dtv*a[j]);
        h[j] = fmaf(dA, h[j], dbx*Bv[j]);
        part = fmaf(h[j], Cv[j], part);
      }
      part += __shfl_xor_sync(~0u, part, 4);
      part += __shfl_xor_sync(~0u, part, 2);
      part += __shfl_xor_sync(~0u, part, 1);
      if (g == 0){
        float zv = sz[t][c];
        sy[t][c] = (part + xcv*Dpd) * (zv * sigmoidf_(zv));
      }
    }
    __syncthreads();

    // ---- write y tile ----
    #pragma unroll
    for (int k=tid; k<STT*SCH; k+=64){
      int t = k >> 3;
      int cc = k & 7;
      y[(r+t0+t)*DI + cg*SCH + cc] = sy[t][cc];
    }
    __syncthreads();
  }
}

// ---------------- host orchestration ----------------------------------------
extern "C" void kernel_launch(void* const* d_in, const int* in_sizes, int n_in,
                              void* d_out, int out_size){
  (void)in_sizes; (void)n_in; (void)out_size;
  const float* x        = (const float*)d_in[0];
  const float* f_in_w   = (const float*)d_in[1];
  const float* f_conv_w = (const float*)d_in[2];
  const float* f_conv_b = (const float*)d_in[3];
  const float* f_xproj  = (const float*)d_in[4];
  const float* f_dt_w   = (const float*)d_in[5];
  const float* f_dt_b   = (const float*)d_in[6];
  const float* f_A_log  = (const float*)d_in[7];
  const float* f_Dp     = (const float*)d_in[8];
  const float* f_out_w  = (const float*)d_in[9];
  const float* b_in_w   = (const float*)d_in[10];
  const float* b_conv_w = (const float*)d_in[11];
  const float* b_conv_b = (const float*)d_in[12];
  const float* b_xproj  = (const float*)d_in[13];
  const float* b_dt_w   = (const float*)d_in[14];
  const float* b_dt_b   = (const float*)d_in[15];
  const float* b_A_log  = (const float*)d_in[16];
  const float* b_Dp     = (const float*)d_in[17];
  const float* b_out_w  = (const float*)d_in[18];
  const float* ln1_g    = (const float*)d_in[19];
  const float* ln1_b    = (const float*)d_in[20];
  const float* ln2_g    = (const float*)d_in[21];
  const float* ln2_b    = (const float*)d_in[22];
  const float* w2       = (const float*)d_in[23];
  const float* b2       = (const float*)d_in[24];

  float *p_xn,*p_xnr,*p_xz,*p_xc,*p_dbl,*p_dt,*p_y,*p_yp,*p_x2;
  cudaGetSymbolAddress((void**)&p_xn,  g_xn);
  cudaGetSymbolAddress((void**)&p_xnr, g_xnr);
  cudaGetSymbolAddress((void**)&p_xz,  g_xz);
  cudaGetSymbolAddress((void**)&p_xc,  g_xc);
  cudaGetSymbolAddress((void**)&p_dbl, g_dbl);
  cudaGetSymbolAddress((void**)&p_dt,  g_dt);
  cudaGetSymbolAddress((void**)&p_y,   g_y);
  cudaGetSymbolAddress((void**)&p_yp,  g_yp);
  cudaGetSymbolAddress((void**)&p_x2,  g_x2);
  float* p_xz1  = p_xz  + (size_t)NTOK*2*DI;
  float* p_xc1  = p_xc  + (size_t)NTOK*DI;
  float* p_dbl1 = p_dbl + (size_t)NTOK*XPN;
  float* p_y1   = p_y   + (size_t)NTOK*DI;
  float* p_yp1  = p_yp  + (size_t)NTOK*DM;

  // 1) LN1 (writes xn and flipped xn)
  ln1_kernel<<<NTOK,256>>>(x, ln1_g, ln1_b);

  // 2) in_proj both directions in one launch
  {
    dim3 grid(2*DI/BN, NTOK/BM, 2);
    sgemm_nt_dual<<<grid,256>>>(p_xn, f_in_w, p_xz,
                                p_xnr, b_in_w, p_xz1,
                                NTOK, 2*DI, DM);
  }

  // 3) depthwise causal conv + silu, both dirs
  {
    dim3 grid((NTOK*DI)/256, 2);
    conv_silu_kernel<<<grid,256>>>(f_conv_w, f_conv_b, b_conv_w, b_conv_b);
  }

  // 4) xproj both directions
  {
    dim3 grid((XPN+BN-1)/BN, NTOK/BM, 2);
    sgemm_nt_dual<<<grid,256>>>(p_xc,  f_xproj, p_dbl,
                                p_xc1, b_xproj, p_dbl1,
                                NTOK, XPN, DI);
  }

  // 5) dt = softplus(dbl16 @ dt_w^T + dt_b), both dirs
  dt_kernel<<<2*NTOK,512>>>(f_dt_w, f_dt_b, b_dt_w, b_dt_b);

  // 6) selective scan, both directions, smem-tiled
  scan_kernel<<<256,64>>>(f_A_log, b_A_log, f_Dp, b_Dp);

  // 7) out_proj both directions
  {
    dim3 grid(DM/BN, NTOK/BM, 2);
    sgemm_nt_dual<<<grid,256>>>(p_y,  f_out_w, p_yp,
                                p_y1, b_out_w, p_yp1,
                                NTOK, DM, DI);
  }

  // 8) x_ssm = yp_f + flip(yp_b); LN2
  combine_ln2_kernel<<<NTOK,256>>>(ln2_g, ln2_b);

  // 9) final: gelu(x2 @ w2^T + b2) -> d_out
  {
    dim3 grid(DM/BN, NTOK/BM);
    sgemm_nt_gelu<<<grid,256>>>(p_x2, w2, (float*)d_out, NTOK, DM, DM, b2);
  }
}